// round 1
// baseline (speedup 1.0000x reference)
#include <cuda_runtime.h>
#include <math.h>

#define N_NODES 100000
#define N_EDGES 1000000
#define KD 128
#define VD 64
#define AGGD 192   // KD + VD

// ---------------- scratch (static device allocations, graph-safe) ----------
__device__ __align__(16) float g_agg[N_NODES * AGGD];
__device__ float g_rowsum[N_NODES];
__device__ float g_sent[N_NODES];
__device__ float g_satt[N_NODES];
__device__ int   g_idx64;

// ---------------- dtype sniff: int64 vs int32 triples ----------------------
// If triples are int64 (values in [0,100000)), every odd 32-bit word is 0.
// If int32, odd words are random indices — all-zero over 256 samples is
// impossible (p = 1e-5 each).
__global__ void sniff_kernel(const int* tri32) {
    if (threadIdx.x == 0 && blockIdx.x == 0) {
        int is64 = 1;
        #pragma unroll 1
        for (int i = 0; i < 256; i++) {
            if (tri32[2 * i + 1] != 0) { is64 = 0; break; }
        }
        g_idx64 = is64;
    }
}

// ---------------- zero the aggregation scratch ------------------------------
__global__ void zero_kernel() {
    int n4 = N_NODES * AGGD / 4;
    float4 z = make_float4(0.f, 0.f, 0.f, 0.f);
    for (int i = blockIdx.x * blockDim.x + threadIdx.x; i < n4;
         i += gridDim.x * blockDim.x)
        reinterpret_cast<float4*>(g_agg)[i] = z;
}

// ---------------- per-node score pre-reduction ------------------------------
// s_ent[n] = dot(ent_feats[n], a_w[0:128]); s_att[n] = dot(att_feats[n], a_w[128:256])
__global__ void score_pre_kernel(const float* __restrict__ ent,
                                 const float* __restrict__ att,
                                 const float* __restrict__ aw) {
    int warp = (blockIdx.x * blockDim.x + threadIdx.x) >> 5;
    int lane = threadIdx.x & 31;
    if (warp >= N_NODES) return;
    float se = 0.f, sa = 0.f;
    #pragma unroll
    for (int t = 0; t < 4; t++) {
        int j = lane + 32 * t;
        se += ent[warp * KD + j] * __ldg(&aw[j]);
        sa += att[warp * KD + j] * __ldg(&aw[KD + j]);
    }
    #pragma unroll
    for (int o = 16; o; o >>= 1) {
        se += __shfl_xor_sync(0xFFFFFFFFu, se, o);
        sa += __shfl_xor_sync(0xFFFFFFFFu, sa, o);
    }
    if (lane == 0) {
        g_sent[warp] = se;
        g_satt[warp] = sa;
        g_rowsum[warp] = 0.f;
    }
}

// ---------------- edge pass: score + weighted scatter-add -------------------
__device__ __forceinline__ void red_v4(float* dst, float a, float b, float c, float d) {
    asm volatile("red.global.add.v4.f32 [%0], {%1, %2, %3, %4};"
                 :: "l"(dst), "f"(a), "f"(b), "f"(c), "f"(d) : "memory");
}

__global__ void edge_kernel(const void* __restrict__ tri,
                            const float* __restrict__ attf,
                            const float* __restrict__ valf,
                            const float* __restrict__ ab) {
    int warp = (blockIdx.x * blockDim.x + threadIdx.x) >> 5;
    int lane = threadIdx.x & 31;
    if (warp >= N_EDGES) return;

    int h = 0, a = 0, v = 0;
    float score = 0.f;
    if (lane == 0) {
        if (g_idx64) {
            const long long* t = reinterpret_cast<const long long*>(tri) + (long long)warp * 3;
            h = (int)t[0]; a = (int)t[1]; v = (int)t[2];
        } else {
            const int* t = reinterpret_cast<const int*>(tri) + warp * 3;
            h = t[0]; a = t[1]; v = t[2];
        }
        float s = g_sent[h] + g_satt[a] + __ldg(&ab[0]);
        s = s > 0.f ? s : 0.2f * s;              // leaky_relu(0.2)
        score = __expf(s);
        atomicAdd(&g_rowsum[h], score);
    }
    h = __shfl_sync(0xFFFFFFFFu, h, 0);
    a = __shfl_sync(0xFFFFFFFFu, a, 0);
    v = __shfl_sync(0xFFFFFFFFu, v, 0);
    score = __shfl_sync(0xFFFFFFFFu, score, 0);

    const float4* a4 = reinterpret_cast<const float4*>(attf) + a * (KD / 4);
    const float4* v4 = reinterpret_cast<const float4*>(valf) + v * (VD / 4);
    float* dst = g_agg + h * AGGD;

    // slots 0..31 -> att features (128 floats)
    {
        float4 x = a4[lane];
        red_v4(dst + lane * 4, x.x * score, x.y * score, x.z * score, x.w * score);
    }
    // slots 32..47 -> val features (64 floats)
    if (lane < 16) {
        float4 x = v4[lane];
        red_v4(dst + KD + lane * 4, x.x * score, x.y * score, x.z * score, x.w * score);
    }
}

// ---------------- node GEMM (192x128) + normalization + ELU -----------------
#define NODES_PER_ITER 8
#define NODE_THREADS 256

__device__ __forceinline__ unsigned long long pack2(float x, float y) {
    unsigned long long r;
    asm("mov.b64 %0, {%1, %2};" : "=l"(r) : "f"(x), "f"(y));
    return r;
}
__device__ __forceinline__ void unpack2(unsigned long long p, float& x, float& y) {
    asm("mov.b64 {%0, %1}, %2;" : "=f"(x), "=f"(y) : "l"(p));
}
__device__ __forceinline__ void ffma2(unsigned long long& d,
                                      unsigned long long a,
                                      unsigned long long b) {
    asm("fma.rn.f32x2 %0, %1, %2, %0;" : "+l"(d) : "l"(a), "l"(b));
}

__global__ void node_kernel(const float* __restrict__ ent,
                            const float* __restrict__ W,
                            float* __restrict__ out) {
    extern __shared__ float sh[];
    float* Wsh   = sh;                 // 192*128 floats = 98304 B
    float* aggsh = sh + AGGD * KD;     // 8*192 floats

    int tid = threadIdx.x;
    // load W into shared (row-major [j][k])
    for (int i = tid; i < AGGD * KD / 4; i += NODE_THREADS)
        reinterpret_cast<float4*>(Wsh)[i] = reinterpret_cast<const float4*>(W)[i];

    int slot = tid >> 5;   // node slot 0..7
    int cg   = tid & 31;   // column group: columns [cg*4, cg*4+3]

    for (int base = blockIdx.x * NODES_PER_ITER; base < N_NODES;
         base += gridDim.x * NODES_PER_ITER) {
        __syncthreads();   // W ready / previous-iter aggsh reads done
        // stage agg rows for 8 nodes
        for (int i = tid; i < NODES_PER_ITER * (AGGD / 4); i += NODE_THREADS) {
            int node = base + i / (AGGD / 4);
            float4 val = (node < N_NODES)
                ? reinterpret_cast<const float4*>(g_agg)[node * (AGGD / 4) + i % (AGGD / 4)]
                : make_float4(0.f, 0.f, 0.f, 0.f);
            reinterpret_cast<float4*>(aggsh)[i] = val;
        }
        __syncthreads();

        int node = base + slot;
        if (node < N_NODES) {
            unsigned long long acc01 = 0ull, acc23 = 0ull;  // {0.f,0.f}
            const float* arow = aggsh + slot * AGGD;
            #pragma unroll 4
            for (int j = 0; j < AGGD; j++) {
                float4 w = reinterpret_cast<const float4*>(Wsh)[j * 32 + cg];
                float aj = arow[j];
                unsigned long long aa = pack2(aj, aj);
                ffma2(acc01, aa, pack2(w.x, w.y));
                ffma2(acc23, aa, pack2(w.z, w.w));
            }
            float c0, c1, c2, c3;
            unpack2(acc01, c0, c1);
            unpack2(acc23, c2, c3);

            float rs = g_rowsum[node];
            float inv = rs > 0.f ? 1.f / rs : 0.f;
            float4 e = reinterpret_cast<const float4*>(ent)[node * (KD / 4) + cg];

            float t0 = c0 * inv + e.x;
            float t1 = c1 * inv + e.y;
            float t2 = c2 * inv + e.z;
            float t3 = c3 * inv + e.w;
            float4 o;
            o.x = t0 > 0.f ? t0 : expm1f(t0);   // elu, alpha=1
            o.y = t1 > 0.f ? t1 : expm1f(t1);
            o.z = t2 > 0.f ? t2 : expm1f(t2);
            o.w = t3 > 0.f ? t3 : expm1f(t3);
            reinterpret_cast<float4*>(out)[node * (KD / 4) + cg] = o;
        }
    }
}

// ---------------- launch ----------------------------------------------------
extern "C" void kernel_launch(void* const* d_in, const int* in_sizes, int n_in,
                              void* d_out, int out_size) {
    const void*  triples = d_in[0];                       // [1e6, 3] int64/int32
    const float* ent     = (const float*)d_in[1];         // [1e5, 128]
    const float* attf    = (const float*)d_in[2];         // [1e5, 128]
    const float* valf    = (const float*)d_in[3];         // [1e5, 64]
    const float* aw      = (const float*)d_in[4];         // [256]
    const float* ab      = (const float*)d_in[5];         // [1]
    const float* W       = (const float*)d_in[6];         // [192, 128]
    float* out           = (float*)d_out;                 // [1e5, 128]

    static bool attr_set = false;
    size_t node_smem = (size_t)(AGGD * KD + NODES_PER_ITER * AGGD) * sizeof(float);
    if (!attr_set) {
        cudaFuncSetAttribute(node_kernel, cudaFuncAttributeMaxDynamicSharedMemorySize,
                             (int)node_smem);
        attr_set = true;
    }

    sniff_kernel<<<1, 32>>>((const int*)triples);
    zero_kernel<<<1024, 256>>>();
    {
        int warps_per_block = 256 / 32;
        int blocks = (N_NODES + warps_per_block - 1) / warps_per_block;
        score_pre_kernel<<<blocks, 256>>>(ent, attf, aw);
    }
    {
        int warps_per_block = 256 / 32;
        int blocks = (N_EDGES + warps_per_block - 1) / warps_per_block;
        edge_kernel<<<blocks, 256>>>(triples, attf, valf, ab);
    }
    node_kernel<<<296, NODE_THREADS, node_smem>>>(ent, W, out);
}

// round 2
// speedup vs baseline: 1.6994x; 1.6994x over previous
#include <cuda_runtime.h>
#include <math.h>

#define N_NODES 100000
#define N_EDGES 1000000
#define KD 128
#define VD 64
#define AGGD 192   // KD + VD

// ---------------- scratch (static device allocations, graph-safe) ----------
__device__ __align__(16) float g_agg[N_NODES * AGGD];
__device__ __align__(16) int4  g_packed[N_EDGES];     // {h, a, v, bitcast(score)}
__device__ float g_rowsum[N_NODES];
__device__ float g_sent[N_NODES];
__device__ float g_satt[N_NODES];
__device__ int   g_idx64;

// ---------------- dtype sniff: int64 vs int32 triples ----------------------
__global__ void sniff_kernel(const int* tri32) {
    if (threadIdx.x == 0 && blockIdx.x == 0) {
        int is64 = 1;
        #pragma unroll 1
        for (int i = 0; i < 256; i++) {
            if (tri32[2 * i + 1] != 0) { is64 = 0; break; }
        }
        g_idx64 = is64;
    }
}

// ---------------- zero the aggregation scratch ------------------------------
__global__ void zero_kernel() {
    int n4 = N_NODES * AGGD / 4;
    float4 z = make_float4(0.f, 0.f, 0.f, 0.f);
    for (int i = blockIdx.x * blockDim.x + threadIdx.x; i < n4;
         i += gridDim.x * blockDim.x)
        reinterpret_cast<float4*>(g_agg)[i] = z;
}

// ---------------- per-node score pre-reduction ------------------------------
__global__ void score_pre_kernel(const float* __restrict__ ent,
                                 const float* __restrict__ att,
                                 const float* __restrict__ aw) {
    int warp = (blockIdx.x * blockDim.x + threadIdx.x) >> 5;
    int lane = threadIdx.x & 31;
    if (warp >= N_NODES) return;
    float se = 0.f, sa = 0.f;
    #pragma unroll
    for (int t = 0; t < 4; t++) {
        int j = lane + 32 * t;
        se += ent[warp * KD + j] * __ldg(&aw[j]);
        sa += att[warp * KD + j] * __ldg(&aw[KD + j]);
    }
    #pragma unroll
    for (int o = 16; o; o >>= 1) {
        se += __shfl_xor_sync(0xFFFFFFFFu, se, o);
        sa += __shfl_xor_sync(0xFFFFFFFFu, sa, o);
    }
    if (lane == 0) {
        g_sent[warp] = se;
        g_satt[warp] = sa;
        g_rowsum[warp] = 0.f;
    }
}

// ---------------- pass A: per-edge score (thread-per-edge, high MLP) --------
__global__ void score_edge_kernel(const void* __restrict__ tri,
                                  const float* __restrict__ ab) {
    int e = blockIdx.x * blockDim.x + threadIdx.x;
    if (e >= N_EDGES) return;
    int h, a, v;
    if (g_idx64) {
        const long long* t = reinterpret_cast<const long long*>(tri) + 3LL * e;
        h = (int)t[0]; a = (int)t[1]; v = (int)t[2];
    } else {
        const int* t = reinterpret_cast<const int*>(tri) + 3 * e;
        h = t[0]; a = t[1]; v = t[2];
    }
    float s = g_sent[h] + g_satt[a] + __ldg(&ab[0]);
    s = s > 0.f ? s : 0.2f * s;                 // leaky_relu(0.2)
    float sc = __expf(s);
    atomicAdd(&g_rowsum[h], sc);
    g_packed[e] = make_int4(h, a, v, __float_as_int(sc));
}

// ---------------- pass B: weighted scatter, 4 edges per warp ----------------
__device__ __forceinline__ void red_v4(float* dst, float a, float b, float c, float d) {
    asm volatile("red.global.add.v4.f32 [%0], {%1, %2, %3, %4};"
                 :: "l"(dst), "f"(a), "f"(b), "f"(c), "f"(d) : "memory");
}

#define EPW 4  // edges per warp

__global__ void scatter_kernel(const float* __restrict__ attf,
                               const float* __restrict__ valf) {
    int warp = (blockIdx.x * blockDim.x + threadIdx.x) >> 5;
    int lane = threadIdx.x & 31;
    int e0 = warp * EPW;
    if (e0 >= N_EDGES) return;

    // lanes 0..3 fetch the packed edge records (coalesced 64B)
    int4 p = make_int4(0, 0, 0, 0);
    if (lane < EPW) p = g_packed[e0 + lane];

    const float4* att4 = reinterpret_cast<const float4*>(attf);
    const float4* val4 = reinterpret_cast<const float4*>(valf);

    int   h[EPW];
    float sc[EPW];
    float4 A[EPW], V[EPW];

    // issue all gathers up front (MLP ~6)
    #pragma unroll
    for (int i = 0; i < EPW; i++) {
        h[i]   = __shfl_sync(0xFFFFFFFFu, p.x, i);
        int a  = __shfl_sync(0xFFFFFFFFu, p.y, i);
        int v  = __shfl_sync(0xFFFFFFFFu, p.z, i);
        sc[i]  = __int_as_float(__shfl_sync(0xFFFFFFFFu, p.w, i));
        A[i] = att4[a * (KD / 4) + lane];
        if (lane < 16) V[i] = val4[v * (VD / 4) + lane];
    }

    #pragma unroll
    for (int i = 0; i < EPW; i++) {
        float* dst = g_agg + h[i] * AGGD;
        float s = sc[i];
        red_v4(dst + lane * 4, A[i].x * s, A[i].y * s, A[i].z * s, A[i].w * s);
        if (lane < 16)
            red_v4(dst + KD + lane * 4, V[i].x * s, V[i].y * s, V[i].z * s, V[i].w * s);
    }
}

// ---------------- node GEMM (192x128) + normalization + ELU -----------------
// 8 warps/block; each warp computes 8 nodes, lane owns 4 output columns.
// W float4 loaded once from smem per (j, lane) and reused across 8 nodes
// -> 16 FFMA2 per LDS.128: FMA-pipe bound (~130K cyc/SM total).
#define NODES_PER_WARP 8
#define NODE_WARPS 8
#define NODE_THREADS (NODE_WARPS * 32)
#define NODES_PER_BLOCK (NODES_PER_WARP * NODE_WARPS)  // 64

__device__ __forceinline__ unsigned long long pack2(float x, float y) {
    unsigned long long r;
    asm("mov.b64 %0, {%1, %2};" : "=l"(r) : "f"(x), "f"(y));
    return r;
}
__device__ __forceinline__ void unpack2(unsigned long long p, float& x, float& y) {
    asm("mov.b64 {%0, %1}, %2;" : "=f"(x), "=f"(y) : "l"(p));
}
__device__ __forceinline__ void ffma2(unsigned long long& d,
                                      unsigned long long a,
                                      unsigned long long b) {
    asm("fma.rn.f32x2 %0, %1, %2, %0;" : "+l"(d) : "l"(a), "l"(b));
}

__global__ void __launch_bounds__(NODE_THREADS, 2)
node_kernel(const float* __restrict__ ent,
            const float* __restrict__ W,
            float* __restrict__ out) {
    extern __shared__ float Wsh[];   // [192][128] = 98304 B

    int tid  = threadIdx.x;
    int wid  = tid >> 5;
    int lane = tid & 31;

    for (int i = tid; i < AGGD * KD / 4; i += NODE_THREADS)
        reinterpret_cast<float4*>(Wsh)[i] = reinterpret_cast<const float4*>(W)[i];
    __syncthreads();

    const float4* agg4 = reinterpret_cast<const float4*>(g_agg);
    int n_tiles = (N_NODES + NODES_PER_BLOCK - 1) / NODES_PER_BLOCK;

    for (int tile = blockIdx.x; tile < n_tiles; tile += gridDim.x) {
        int nbase = tile * NODES_PER_BLOCK + wid * NODES_PER_WARP;

        unsigned long long acc01[NODES_PER_WARP], acc23[NODES_PER_WARP];
        #pragma unroll
        for (int n = 0; n < NODES_PER_WARP; n++) { acc01[n] = 0ull; acc23[n] = 0ull; }

        #pragma unroll 1
        for (int j = 0; j < AGGD; j += 4) {
            // stage agg[node][j..j+3] per node (broadcast LDG via L1/L2 stream)
            float4 aj[NODES_PER_WARP];
            #pragma unroll
            for (int n = 0; n < NODES_PER_WARP; n++) {
                int node = nbase + n;
                aj[n] = (node < N_NODES)
                    ? __ldg(&agg4[node * (AGGD / 4) + (j >> 2)])
                    : make_float4(0.f, 0.f, 0.f, 0.f);
            }
            #pragma unroll
            for (int jj = 0; jj < 4; jj++) {
                float4 w = reinterpret_cast<const float4*>(Wsh)[(j + jj) * 32 + lane];
                unsigned long long w01 = pack2(w.x, w.y);
                unsigned long long w23 = pack2(w.z, w.w);
                #pragma unroll
                for (int n = 0; n < NODES_PER_WARP; n++) {
                    float a = (jj == 0) ? aj[n].x : (jj == 1) ? aj[n].y
                             : (jj == 2) ? aj[n].z : aj[n].w;
                    unsigned long long aa = pack2(a, a);
                    ffma2(acc01[n], aa, w01);
                    ffma2(acc23[n], aa, w23);
                }
            }
        }

        #pragma unroll
        for (int n = 0; n < NODES_PER_WARP; n++) {
            int node = nbase + n;
            if (node >= N_NODES) break;
            float c0, c1, c2, c3;
            unpack2(acc01[n], c0, c1);
            unpack2(acc23[n], c2, c3);

            float rs = g_rowsum[node];
            float inv = rs > 0.f ? 1.f / rs : 0.f;
            float4 e = reinterpret_cast<const float4*>(ent)[node * (KD / 4) + lane];

            float t0 = c0 * inv + e.x;
            float t1 = c1 * inv + e.y;
            float t2 = c2 * inv + e.z;
            float t3 = c3 * inv + e.w;
            float4 o;
            o.x = t0 > 0.f ? t0 : expm1f(t0);   // elu, alpha=1
            o.y = t1 > 0.f ? t1 : expm1f(t1);
            o.z = t2 > 0.f ? t2 : expm1f(t2);
            o.w = t3 > 0.f ? t3 : expm1f(t3);
            reinterpret_cast<float4*>(out)[node * (KD / 4) + lane] = o;
        }
    }
}

// ---------------- launch ----------------------------------------------------
extern "C" void kernel_launch(void* const* d_in, const int* in_sizes, int n_in,
                              void* d_out, int out_size) {
    const void*  triples = d_in[0];                       // [1e6, 3] int64/int32
    const float* ent     = (const float*)d_in[1];         // [1e5, 128]
    const float* attf    = (const float*)d_in[2];         // [1e5, 128]
    const float* valf    = (const float*)d_in[3];         // [1e5, 64]
    const float* aw      = (const float*)d_in[4];         // [256]
    const float* ab      = (const float*)d_in[5];         // [1]
    const float* W       = (const float*)d_in[6];         // [192, 128]
    float* out           = (float*)d_out;                 // [1e5, 128]

    static bool attr_set = false;
    size_t node_smem = (size_t)(AGGD * KD) * sizeof(float);   // 98304
    if (!attr_set) {
        cudaFuncSetAttribute(node_kernel, cudaFuncAttributeMaxDynamicSharedMemorySize,
                             (int)node_smem);
        attr_set = true;
    }

    sniff_kernel<<<1, 32>>>((const int*)triples);
    zero_kernel<<<1024, 256>>>();
    {
        int blocks = (N_NODES + 7) / 8;                   // warp per node
        score_pre_kernel<<<blocks, 256>>>(ent, attf, aw);
    }
    score_edge_kernel<<<(N_EDGES + 255) / 256, 256>>>(triples, ab);
    {
        int warps = N_EDGES / EPW;                        // 250000
        scatter_kernel<<<(warps * 32 + 255) / 256, 256>>>(attf, valf);
    }
    node_kernel<<<296, NODE_THREADS, node_smem>>>(ent, W, out);
}

// round 3
// speedup vs baseline: 1.9779x; 1.1638x over previous
#include <cuda_runtime.h>
#include <math.h>

#define N_NODES 100000
#define N_EDGES 1000000
#define KD 128
#define VD 64
#define AGGD 192   // KD + VD
#define NBLK 391   // ceil(N_NODES / 256)

// ---------------- scratch (static device allocations, graph-safe) ----------
__device__ __align__(16) float g_agg[N_NODES * AGGD];
__device__ __align__(16) int4  g_packed[N_EDGES];   // {h, a, v, bitcast(score)}
__device__ __align__(16) int4  g_csr[N_EDGES];      // CSR-ordered copies
__device__ float g_rowsum[N_NODES];
__device__ float g_sent[N_NODES];
__device__ float g_satt[N_NODES];
__device__ int   g_deg[N_NODES];
__device__ int   g_off[N_NODES];
__device__ int   g_cursor[N_NODES];
__device__ int   g_bsum[NBLK];
__device__ int   g_boff[NBLK];
__device__ int   g_idx64;

// ---------------- dtype sniff: int64 vs int32 triples ----------------------
__global__ void sniff_kernel(const int* tri32) {
    if (threadIdx.x == 0 && blockIdx.x == 0) {
        int is64 = 1;
        #pragma unroll 1
        for (int i = 0; i < 256; i++) {
            if (tri32[2 * i + 1] != 0) { is64 = 0; break; }
        }
        g_idx64 = is64;
    }
}

// ---------------- per-node score pre-reduction + counters reset -------------
__global__ void score_pre_kernel(const float* __restrict__ ent,
                                 const float* __restrict__ att,
                                 const float* __restrict__ aw) {
    int warp = (blockIdx.x * blockDim.x + threadIdx.x) >> 5;
    int lane = threadIdx.x & 31;
    if (warp >= N_NODES) return;
    float se = 0.f, sa = 0.f;
    #pragma unroll
    for (int t = 0; t < 4; t++) {
        int j = lane + 32 * t;
        se += ent[warp * KD + j] * __ldg(&aw[j]);
        sa += att[warp * KD + j] * __ldg(&aw[KD + j]);
    }
    #pragma unroll
    for (int o = 16; o; o >>= 1) {
        se += __shfl_xor_sync(0xFFFFFFFFu, se, o);
        sa += __shfl_xor_sync(0xFFFFFFFFu, sa, o);
    }
    if (lane == 0) {
        g_sent[warp] = se;
        g_satt[warp] = sa;
        g_rowsum[warp] = 0.f;
        g_deg[warp] = 0;
    }
}

// ---------------- pass A: per-edge score + degree histogram -----------------
__global__ void score_edge_kernel(const void* __restrict__ tri,
                                  const float* __restrict__ ab) {
    int e = blockIdx.x * blockDim.x + threadIdx.x;
    if (e >= N_EDGES) return;
    int h, a, v;
    if (g_idx64) {
        const long long* t = reinterpret_cast<const long long*>(tri) + 3LL * e;
        h = (int)t[0]; a = (int)t[1]; v = (int)t[2];
    } else {
        const int* t = reinterpret_cast<const int*>(tri) + 3 * e;
        h = t[0]; a = t[1]; v = t[2];
    }
    float s = g_sent[h] + g_satt[a] + __ldg(&ab[0]);
    s = s > 0.f ? s : 0.2f * s;                 // leaky_relu(0.2)
    float sc = __expf(s);
    atomicAdd(&g_rowsum[h], sc);
    atomicAdd(&g_deg[h], 1);
    g_packed[e] = make_int4(h, a, v, __float_as_int(sc));
}

// ---------------- 3-phase exclusive scan over degrees -----------------------
__global__ void scan_a_kernel() {
    __shared__ int sh[256];
    int t = threadIdx.x, b = blockIdx.x;
    int node = b * 256 + t;
    int v = (node < N_NODES) ? g_deg[node] : 0;
    sh[t] = v;
    __syncthreads();
    #pragma unroll
    for (int d = 128; d; d >>= 1) {
        if (t < d) sh[t] += sh[t + d];
        __syncthreads();
    }
    if (t == 0) g_bsum[b] = sh[0];
}

__global__ void scan_b_kernel() {
    __shared__ int sh[512];
    int t = threadIdx.x;
    int v = (t < NBLK) ? g_bsum[t] : 0;
    sh[t] = v;
    __syncthreads();
    #pragma unroll
    for (int d = 1; d < 512; d <<= 1) {
        int x = (t >= d) ? sh[t - d] : 0;
        __syncthreads();
        sh[t] += x;
        __syncthreads();
    }
    if (t < NBLK) g_boff[t] = sh[t] - v;   // exclusive
}

__global__ void scan_c_kernel() {
    __shared__ int sh[256];
    int t = threadIdx.x, b = blockIdx.x;
    int node = b * 256 + t;
    int v = (node < N_NODES) ? g_deg[node] : 0;
    sh[t] = v;
    __syncthreads();
    #pragma unroll
    for (int d = 1; d < 256; d <<= 1) {
        int x = (t >= d) ? sh[t - d] : 0;
        __syncthreads();
        sh[t] += x;
        __syncthreads();
    }
    if (node < N_NODES) {
        int off = g_boff[b] + sh[t] - v;   // exclusive within block + block base
        g_off[node] = off;
        g_cursor[node] = off;
    }
}

// ---------------- pass B: permute records into CSR order --------------------
__global__ void fill_kernel() {
    int e = blockIdx.x * blockDim.x + threadIdx.x;
    if (e >= N_EDGES) return;
    int4 p = g_packed[e];
    int pos = atomicAdd(&g_cursor[p.x], 1);
    g_csr[pos] = p;
}

// ---------------- pass C: gather-side weighted aggregation (no atomics) -----
__global__ void aggregate_kernel(const float* __restrict__ attf,
                                 const float* __restrict__ valf) {
    int warp = (blockIdx.x * blockDim.x + threadIdx.x) >> 5;
    int lane = threadIdx.x & 31;
    if (warp >= N_NODES) return;
    int beg = g_off[warp];
    int deg = g_deg[warp];

    const float4* att4 = reinterpret_cast<const float4*>(attf);
    const float4* val4 = reinterpret_cast<const float4*>(valf);

    float4 accA = make_float4(0.f, 0.f, 0.f, 0.f);
    float4 accV = make_float4(0.f, 0.f, 0.f, 0.f);

    for (int base = 0; base < deg; base += 32) {
        int4 r = make_int4(0, 0, 0, 0);
        if (base + lane < deg) r = g_csr[beg + base + lane];
        int m = min(32, deg - base);
        for (int i = 0; i < m; i++) {
            int   a = __shfl_sync(0xFFFFFFFFu, r.y, i);
            int   v = __shfl_sync(0xFFFFFFFFu, r.z, i);
            float s = __int_as_float(__shfl_sync(0xFFFFFFFFu, r.w, i));
            float4 A = __ldg(&att4[a * (KD / 4) + lane]);
            accA.x += A.x * s; accA.y += A.y * s;
            accA.z += A.z * s; accA.w += A.w * s;
            if (lane < 16) {
                float4 V = __ldg(&val4[v * (VD / 4) + lane]);
                accV.x += V.x * s; accV.y += V.y * s;
                accV.z += V.z * s; accV.w += V.w * s;
            }
        }
    }

    float* dst = g_agg + warp * AGGD;
    *reinterpret_cast<float4*>(dst + lane * 4) = accA;
    if (lane < 16)
        *reinterpret_cast<float4*>(dst + KD + lane * 4) = accV;
}

// ---------------- node GEMM (192x128) + normalization + ELU -----------------
#define NODES_PER_WARP 8
#define NODE_WARPS 8
#define NODE_THREADS (NODE_WARPS * 32)
#define NODES_PER_BLOCK (NODES_PER_WARP * NODE_WARPS)  // 64

__device__ __forceinline__ unsigned long long pack2(float x, float y) {
    unsigned long long r;
    asm("mov.b64 %0, {%1, %2};" : "=l"(r) : "f"(x), "f"(y));
    return r;
}
__device__ __forceinline__ void unpack2(unsigned long long p, float& x, float& y) {
    asm("mov.b64 {%0, %1}, %2;" : "=f"(x), "=f"(y) : "l"(p));
}
__device__ __forceinline__ void ffma2(unsigned long long& d,
                                      unsigned long long a,
                                      unsigned long long b) {
    asm("fma.rn.f32x2 %0, %1, %2, %0;" : "+l"(d) : "l"(a), "l"(b));
}

__global__ void __launch_bounds__(NODE_THREADS, 2)
node_kernel(const float* __restrict__ ent,
            const float* __restrict__ W,
            float* __restrict__ out) {
    extern __shared__ float Wsh[];   // [192][128] = 98304 B

    int tid  = threadIdx.x;
    int wid  = tid >> 5;
    int lane = tid & 31;

    for (int i = tid; i < AGGD * KD / 4; i += NODE_THREADS)
        reinterpret_cast<float4*>(Wsh)[i] = reinterpret_cast<const float4*>(W)[i];
    __syncthreads();

    const float4* agg4 = reinterpret_cast<const float4*>(g_agg);
    int n_tiles = (N_NODES + NODES_PER_BLOCK - 1) / NODES_PER_BLOCK;

    for (int tile = blockIdx.x; tile < n_tiles; tile += gridDim.x) {
        int nbase = tile * NODES_PER_BLOCK + wid * NODES_PER_WARP;

        unsigned long long acc01[NODES_PER_WARP], acc23[NODES_PER_WARP];
        #pragma unroll
        for (int n = 0; n < NODES_PER_WARP; n++) { acc01[n] = 0ull; acc23[n] = 0ull; }

        #pragma unroll 1
        for (int j = 0; j < AGGD; j += 4) {
            float4 aj[NODES_PER_WARP];
            #pragma unroll
            for (int n = 0; n < NODES_PER_WARP; n++) {
                int node = nbase + n;
                aj[n] = (node < N_NODES)
                    ? __ldg(&agg4[node * (AGGD / 4) + (j >> 2)])
                    : make_float4(0.f, 0.f, 0.f, 0.f);
            }
            #pragma unroll
            for (int jj = 0; jj < 4; jj++) {
                float4 w = reinterpret_cast<const float4*>(Wsh)[(j + jj) * 32 + lane];
                unsigned long long w01 = pack2(w.x, w.y);
                unsigned long long w23 = pack2(w.z, w.w);
                #pragma unroll
                for (int n = 0; n < NODES_PER_WARP; n++) {
                    float a = (jj == 0) ? aj[n].x : (jj == 1) ? aj[n].y
                             : (jj == 2) ? aj[n].z : aj[n].w;
                    unsigned long long aa = pack2(a, a);
                    ffma2(acc01[n], aa, w01);
                    ffma2(acc23[n], aa, w23);
                }
            }
        }

        #pragma unroll
        for (int n = 0; n < NODES_PER_WARP; n++) {
            int node = nbase + n;
            if (node >= N_NODES) break;
            float c0, c1, c2, c3;
            unpack2(acc01[n], c0, c1);
            unpack2(acc23[n], c2, c3);

            float rs = g_rowsum[node];
            float inv = rs > 0.f ? 1.f / rs : 0.f;
            float4 e = reinterpret_cast<const float4*>(ent)[node * (KD / 4) + lane];

            float t0 = c0 * inv + e.x;
            float t1 = c1 * inv + e.y;
            float t2 = c2 * inv + e.z;
            float t3 = c3 * inv + e.w;
            float4 o;
            o.x = t0 > 0.f ? t0 : expm1f(t0);   // elu, alpha=1
            o.y = t1 > 0.f ? t1 : expm1f(t1);
            o.z = t2 > 0.f ? t2 : expm1f(t2);
            o.w = t3 > 0.f ? t3 : expm1f(t3);
            reinterpret_cast<float4*>(out)[node * (KD / 4) + lane] = o;
        }
    }
}

// ---------------- launch ----------------------------------------------------
extern "C" void kernel_launch(void* const* d_in, const int* in_sizes, int n_in,
                              void* d_out, int out_size) {
    const void*  triples = d_in[0];                       // [1e6, 3] int64/int32
    const float* ent     = (const float*)d_in[1];         // [1e5, 128]
    const float* attf    = (const float*)d_in[2];         // [1e5, 128]
    const float* valf    = (const float*)d_in[3];         // [1e5, 64]
    const float* aw      = (const float*)d_in[4];         // [256]
    const float* ab      = (const float*)d_in[5];         // [1]
    const float* W       = (const float*)d_in[6];         // [192, 128]
    float* out           = (float*)d_out;                 // [1e5, 128]

    static bool attr_set = false;
    size_t node_smem = (size_t)(AGGD * KD) * sizeof(float);   // 98304
    if (!attr_set) {
        cudaFuncSetAttribute(node_kernel, cudaFuncAttributeMaxDynamicSharedMemorySize,
                             (int)node_smem);
        attr_set = true;
    }

    sniff_kernel<<<1, 32>>>((const int*)triples);
    score_pre_kernel<<<(N_NODES + 7) / 8, 256>>>(ent, attf, aw);
    score_edge_kernel<<<(N_EDGES + 255) / 256, 256>>>(triples, ab);
    scan_a_kernel<<<NBLK, 256>>>();
    scan_b_kernel<<<1, 512>>>();
    scan_c_kernel<<<NBLK, 256>>>();
    fill_kernel<<<(N_EDGES + 255) / 256, 256>>>();
    aggregate_kernel<<<(N_NODES * 32 + 255) / 256, 256>>>(attf, valf);
    node_kernel<<<296, NODE_THREADS, node_smem>>>(ent, W, out);
}